// round 2
// baseline (speedup 1.0000x reference)
#include <cuda_runtime.h>
#include <cstdint>
#include <cstring>

// ---------------- problem dims ----------------
#define M_DIM 4096
#define K_DIM 4096
#define N_DIM 11008

#define TILE_M 128
#define TILE_N 256
#define TILE_K 32
#define STAGES 4
#define K_ITERS (K_DIM / TILE_K)       // 128
#define M_TILES (M_DIM / TILE_M)       // 32
#define N_TILES (N_DIM / TILE_N)       // 43

#define A_STAGE_BYTES (TILE_M * TILE_K * 4)   // 16384
#define B_STAGE_BYTES (TILE_N * TILE_K * 4)   // 32768
#define CHUNK_BYTES   (A_STAGE_BYTES + B_STAGE_BYTES)

// smem: barriers then buffers
#define SM_FULL  64
#define SM_EMPTY 128
#define SM_A     1024
#define SM_B     (SM_A + STAGES * A_STAGE_BYTES)       // 66560
#define SMEM_BYTES (SM_B + STAGES * B_STAGE_BYTES)     // 197632

// ---------------- scratch (device globals; allocation is forbidden) ----------------
// A in fragment-major layout: [mblock(32)][kchunk(128)][4096 floats]
//   chunk = 8 mtiles x 4 ksteps blocks of 128 floats; block = lane-major:
//   lane's 4 floats = A(r,c), A(r+8,c), A(r,c+4), A(r+8,c+4), r=lane>>2, c=lane&3
__device__ float g_xs[(size_t)M_DIM * K_DIM];
// B in fragment-major layout: [nblock(43)][kchunk(128)][8192 floats]
//   chunk = 16 pairblocks x 4 ksteps blocks of 128 floats; block = lane-major:
//   lane's 4 floats = B(n=r,k=c), B(r,c+4), B(r+8,c), B(r+8,c+4) for the 16-row pair
__device__ float g_w[(size_t)N_DIM * K_DIM];
__device__ float g_c[M_DIM];            // c[m] = sum_k x[m,k]*s[g]*zp[g]

// ---------------- PTX helpers (generic sm_90-level only; NO 'a' features) ----------------
__device__ __forceinline__ uint32_t smem_u32(const void* p) {
    uint32_t a;
    asm("{ .reg .u64 t; cvta.to.shared.u64 t, %1; cvt.u32.u64 %0, t; }" : "=r"(a) : "l"(p));
    return a;
}

#define MBAR_INIT(addr, cnt) \
    asm volatile("mbarrier.init.shared.b64 [%0], %1;" :: "r"(addr), "r"((uint32_t)(cnt)) : "memory")
#define MBAR_EXPECT_TX(addr, bytes) \
    asm volatile("mbarrier.arrive.expect_tx.shared.b64 _, [%0], %1;" :: "r"(addr), "r"((uint32_t)(bytes)) : "memory")
#define MBAR_ARRIVE(addr) \
    asm volatile("mbarrier.arrive.shared.b64 _, [%0];" :: "r"(addr) : "memory")

#define MBAR_WAIT(addr, parity) do {                                              \
    uint32_t _m = (addr); uint32_t _p = (parity); uint32_t _done;                 \
    asm volatile("{ .reg .pred p;"                                                \
        " mbarrier.try_wait.parity.shared.b64 p, [%1], %2;"                       \
        " selp.b32 %0, 1, 0, p; }" : "=r"(_done) : "r"(_m), "r"(_p) : "memory");  \
    if (!_done) {                                                                 \
        asm volatile("{ .reg .pred P1;"                                           \
            " WL_%=:"                                                             \
            " mbarrier.try_wait.parity.shared.b64 P1, [%0], %1;"                  \
            " @P1 bra.uni WD_%=;"                                                 \
            " bra.uni WL_%=;"                                                     \
            " WD_%=: }" :: "r"(_m), "r"(_p) : "memory");                          \
    }                                                                             \
} while (0)

// 1-D bulk async copy gmem -> smem with mbarrier tx completion (sm_90 generic)
#define BULK_G2S(dst, src, bytes, mbar)                                           \
    asm volatile("cp.async.bulk.shared::cluster.global.mbarrier::complete_tx::bytes " \
                 "[%0], [%1], %2, [%3];"                                          \
                 :: "r"(dst), "l"(src), "r"((uint32_t)(bytes)), "r"(mbar) : "memory")

__device__ __forceinline__ float tf32r(float x) {
    uint32_t u;
    asm("cvt.rna.tf32.f32 %0, %1;" : "=r"(u) : "f"(x));
    return __uint_as_float(u);
}

// m16n8k8 tf32 mma (sm_80 generic). acc: float[4], a: b32[4], b: b32[2]
#define MMA_TF32(acc, au, b0, b1)                                                 \
    asm volatile("mma.sync.aligned.m16n8k8.row.col.f32.tf32.tf32.f32 "            \
        "{%0,%1,%2,%3}, {%4,%5,%6,%7}, {%8,%9}, {%0,%1,%2,%3};"                   \
        : "+f"((acc)[0]), "+f"((acc)[1]), "+f"((acc)[2]), "+f"((acc)[3])          \
        : "r"((au)[0]), "r"((au)[1]), "r"((au)[2]), "r"((au)[3]),                 \
          "r"(b0), "r"(b1))

__device__ __forceinline__ uint32_t fu(float x) { return __float_as_uint(x); }

// ---------------- prep: c[m] = sum_k x[m,k] * s[k/64] * zp[k/64] ----------------
__global__ void __launch_bounds__(256) prep_c_kernel(const float* __restrict__ x,
                                                     const float* __restrict__ scales,
                                                     const float* __restrict__ zps) {
    const int m = blockIdx.x;
    const int tid = threadIdx.x;
    const float4* xr = reinterpret_cast<const float4*>(x + (size_t)m * K_DIM);
    float acc = 0.f;
#pragma unroll
    for (int i = 0; i < 4; i++) {
        int v4 = tid + i * 256;            // float4 index 0..1023
        int g = v4 >> 4;                   // group = (v4*4)>>6
        float zs = scales[g] * zps[g];
        float4 v = xr[v4];
        acc += (v.x + v.y + v.z + v.w) * zs;
    }
    __shared__ float red[256];
    red[tid] = acc;
    __syncthreads();
    for (int s = 128; s > 0; s >>= 1) {
        if (tid < s) red[tid] += red[tid + s];
        __syncthreads();
    }
    if (tid == 0) g_c[m] = red[0];
}

// ---------------- prep: x' = tf32(x * s) into fragment-major layout ----------------
__global__ void __launch_bounds__(256) prep_x_kernel(const float* __restrict__ x,
                                                     const float* __restrict__ scales) {
    const int kc = blockIdx.x;             // kchunk 0..127
    const int mb = blockIdx.y;             // mblock 0..31
    const int tid = threadIdx.x;
    __shared__ float sm[TILE_M * TILE_K];  // [row][col] 128x32

    const float s = scales[kc >> 1];       // group = 64 elems = 2 kchunks
    const float* xsrc = x + (size_t)mb * 128 * K_DIM + kc * 32;
#pragma unroll
    for (int i = 0; i < 16; i++) {
        int idx = tid + i * 256;           // 0..4095
        int row = idx >> 5, col = idx & 31;
        sm[idx] = tf32r(xsrc[(size_t)row * K_DIM + col] * s);
    }
    __syncthreads();

    const int lane = tid & 31, w = tid >> 5;
    float* dst = g_xs + ((size_t)mb * K_ITERS + kc) * 4096;
    const int r = lane >> 2, c = lane & 3;
#pragma unroll
    for (int i = 0; i < 4; i++) {
        int bi = w * 4 + i;                // block 0..31
        int mt = bi >> 2, ks = bi & 3;
        int rr = mt * 16 + r, cc = ks * 8 + c;
        float4 v;
        v.x = sm[rr * 32 + cc];
        v.y = sm[(rr + 8) * 32 + cc];
        v.z = sm[rr * 32 + cc + 4];
        v.w = sm[(rr + 8) * 32 + cc + 4];
        *reinterpret_cast<float4*>(dst + bi * 128 + lane * 4) = v;
    }
}

// ---------------- prep: int4 -> fp32 (exact) into fragment-major layout ----------------
__global__ void __launch_bounds__(256) prep_w_kernel(const int* __restrict__ pw) {
    const int kc = blockIdx.x;             // kchunk 0..127
    const int nb = blockIdx.y;             // nblock 0..42
    const int tid = threadIdx.x;
    __shared__ float sm[TILE_N * TILE_K];  // [n][k] 256x32 = 32KB

    const int* src = pw + (size_t)nb * 256 * (K_DIM / 2) + kc * 16;
#pragma unroll
    for (int i = 0; i < 16; i++) {
        int idx = tid + i * 256;           // 0..4095 int32s
        int n = idx >> 4, jj = idx & 15;
        int b = src[(size_t)n * (K_DIM / 2) + jj] & 255;
        sm[n * 32 + jj * 2]     = (float)(((b & 15) ^ 8) - 8);
        sm[n * 32 + jj * 2 + 1] = (float)((((b >> 4) & 15) ^ 8) - 8);
    }
    __syncthreads();

    const int lane = tid & 31, w = tid >> 5;
    float* dst = g_w + ((size_t)nb * K_ITERS + kc) * 8192;
    const int r = lane >> 2, c = lane & 3;
#pragma unroll
    for (int i = 0; i < 8; i++) {
        int bi = w * 8 + i;                // block 0..63
        int p = bi >> 2, ks = bi & 3;
        int nr = p * 16 + r, cc = ks * 8 + c;
        float4 v;
        v.x = sm[nr * 32 + cc];
        v.y = sm[nr * 32 + cc + 4];
        v.z = sm[(nr + 8) * 32 + cc];
        v.w = sm[(nr + 8) * 32 + cc + 4];
        *reinterpret_cast<float4*>(dst + bi * 128 + lane * 4) = v;
    }
}

// ---------------- GEMM: out = x' @ w4^T + (bias - c) ----------------
__global__ void __launch_bounds__(512, 1) gemm_kernel(const float* __restrict__ bias,
                                                      float* __restrict__ out) {
    extern __shared__ char smem[];
    const uint32_t sb = smem_u32(smem);
    const int tid = threadIdx.x;
    const int lane = tid & 31;
    const int wid = tid >> 5;
    const int wm = wid >> 2;               // 0..3
    const int wn = wid & 3;                // 0..3

    const int bid = blockIdx.x;
    const int nb = bid / M_TILES;          // m fastest: consecutive CTAs share B panel
    const int mb = bid % M_TILES;

    const float* gA = g_xs + (size_t)mb * K_ITERS * 4096;
    const float* gB = g_w + (size_t)nb * K_ITERS * 8192;

    if (tid == 0) {
#pragma unroll
        for (int s = 0; s < STAGES; s++) {
            MBAR_INIT(sb + SM_FULL + 8 * s, 1);
            MBAR_INIT(sb + SM_EMPTY + 8 * s, 16);
        }
        asm volatile("fence.mbarrier_init.release.cluster;" ::: "memory");
    }
    __syncthreads();

    if (tid == 0) {
#pragma unroll
        for (int s = 0; s < STAGES; s++) {  // fill all stages
            MBAR_EXPECT_TX(sb + SM_FULL + 8 * s, CHUNK_BYTES);
            BULK_G2S(sb + SM_A + s * A_STAGE_BYTES, gA + (size_t)s * 4096, A_STAGE_BYTES, sb + SM_FULL + 8 * s);
            BULK_G2S(sb + SM_B + s * B_STAGE_BYTES, gB + (size_t)s * 8192, B_STAGE_BYTES, sb + SM_FULL + 8 * s);
        }
    }

    float acc[2][8][4];
#pragma unroll
    for (int a = 0; a < 2; a++)
#pragma unroll
        for (int b = 0; b < 8; b++)
#pragma unroll
            for (int d = 0; d < 4; d++) acc[a][b][d] = 0.f;

    const int lane4 = lane * 4;
    int ph = 0;

    for (int itb = 0; itb < K_ITERS / STAGES; itb++) {
#pragma unroll
        for (int s = 0; s < STAGES; s++) {
            const int it = itb * STAGES + s;
            MBAR_WAIT(sb + SM_FULL + 8 * s, ph);

            const float* As = reinterpret_cast<const float*>(smem + SM_A + s * A_STAGE_BYTES);
            const float* Bs = reinterpret_cast<const float*>(smem + SM_B + s * B_STAGE_BYTES);
#pragma unroll
            for (int ks = 0; ks < 4; ks++) {
                float4 a0 = *reinterpret_cast<const float4*>(As + ((wm * 2 + 0) * 4 + ks) * 128 + lane4);
                float4 a1 = *reinterpret_cast<const float4*>(As + ((wm * 2 + 1) * 4 + ks) * 128 + lane4);
                uint32_t a0u[4] = {fu(a0.x), fu(a0.y), fu(a0.z), fu(a0.w)};
                uint32_t a1u[4] = {fu(a1.x), fu(a1.y), fu(a1.z), fu(a1.w)};
#pragma unroll
                for (int j = 0; j < 4; j++) {
                    float4 bv = *reinterpret_cast<const float4*>(Bs + ((wn * 4 + j) * 4 + ks) * 128 + lane4);
                    uint32_t b0 = fu(bv.x), b1 = fu(bv.y), b2 = fu(bv.z), b3 = fu(bv.w);
                    MMA_TF32(acc[0][2 * j],     a0u, b0, b1);
                    MMA_TF32(acc[0][2 * j + 1], a0u, b2, b3);
                    MMA_TF32(acc[1][2 * j],     a1u, b0, b1);
                    MMA_TF32(acc[1][2 * j + 1], a1u, b2, b3);
                }
            }
            __syncwarp();
            if (lane == 0) MBAR_ARRIVE(sb + SM_EMPTY + 8 * s);

            if (tid == 0 && it + STAGES < K_ITERS) {
                MBAR_WAIT(sb + SM_EMPTY + 8 * s, ph);
                MBAR_EXPECT_TX(sb + SM_FULL + 8 * s, CHUNK_BYTES);
                BULK_G2S(sb + SM_A + s * A_STAGE_BYTES, gA + (size_t)(it + STAGES) * 4096, A_STAGE_BYTES, sb + SM_FULL + 8 * s);
                BULK_G2S(sb + SM_B + s * B_STAGE_BYTES, gB + (size_t)(it + STAGES) * 8192, B_STAGE_BYTES, sb + SM_FULL + 8 * s);
            }
        }
        ph ^= 1;
    }

    // ---- epilogue: out = acc + bias[n] - c[m] ----
    const int c0 = (lane & 3) * 2;
    const int r0 = lane >> 2;
    const int ncol = nb * 256 + wn * 64 + c0;
    float2 bv[8];
#pragma unroll
    for (int j = 0; j < 8; j++) bv[j] = *reinterpret_cast<const float2*>(bias + ncol + j * 8);

    const int mrow = mb * 128 + wm * 32 + r0;
    float cm[4];
#pragma unroll
    for (int i = 0; i < 4; i++) cm[i] = g_c[mrow + i * 8];

#pragma unroll
    for (int mt = 0; mt < 2; mt++) {
#pragma unroll
        for (int h = 0; h < 2; h++) {
            const float cmv = cm[mt * 2 + h];
            float* orow = out + (size_t)(mrow + mt * 16 + h * 8) * N_DIM + ncol;
#pragma unroll
            for (int j = 0; j < 8; j++) {
                float2 v;
                v.x = acc[mt][j][h * 2 + 0] + bv[j].x - cmv;
                v.y = acc[mt][j][h * 2 + 1] + bv[j].y - cmv;
                *reinterpret_cast<float2*>(orow + j * 8) = v;
            }
        }
    }
}

// ---------------- host ----------------
extern "C" void kernel_launch(void* const* d_in, const int* in_sizes, int n_in,
                              void* d_out, int out_size) {
    const float* x      = (const float*)d_in[0];
    const int*   pw     = (const int*)d_in[1];
    const float* scales = (const float*)d_in[2];
    const float* zps    = (const float*)d_in[3];
    const float* bias   = (const float*)d_in[4];
    float* out = (float*)d_out;

    cudaFuncSetAttribute(gemm_kernel, cudaFuncAttributeMaxDynamicSharedMemorySize, SMEM_BYTES);

    prep_c_kernel<<<M_DIM, 256>>>(x, scales, zps);
    prep_x_kernel<<<dim3(K_ITERS, M_TILES), 256>>>(x, scales);
    prep_w_kernel<<<dim3(K_ITERS, N_TILES), 256>>>(pw);
    gemm_kernel<<<M_TILES * N_TILES, 512, SMEM_BYTES>>>(bias, out);
}

// round 5
// speedup vs baseline: 1.7288x; 1.7288x over previous
#include <cuda_runtime.h>
#include <cuda_fp16.h>
#include <cstdint>

// ---------------- problem dims ----------------
#define M_DIM 4096
#define K_DIM 4096
#define N_DIM 11008

#define TILE_M 128
#define TILE_N 256
#define TILE_K 32
#define STAGES 4
#define K_ITERS (K_DIM / TILE_K)       // 128
#define M_TILES (M_DIM / TILE_M)       // 32
#define N_TILES (N_DIM / TILE_N)       // 43

#define A_CHUNK_HALFS (TILE_M * TILE_K)       // 4096
#define B_CHUNK_HALFS (TILE_N * TILE_K)       // 8192
#define A_STAGE_BYTES (A_CHUNK_HALFS * 2)     // 8192
#define B_STAGE_BYTES (B_CHUNK_HALFS * 2)     // 16384
#define CHUNK_BYTES   (A_STAGE_BYTES + B_STAGE_BYTES)

#define SM_FULL  64
#define SM_EMPTY 128
#define SM_A     1024
#define SM_B     (SM_A + STAGES * A_STAGE_BYTES)       // 33792
#define SMEM_BYTES (SM_B + STAGES * B_STAGE_BYTES)     // 99328

// ---------------- scratch (device globals; allocation forbidden) ----------------
// A fragment-major: [mblock(32)][kchunk(128)][ (mtile*2+kstep)(16) ][lane(32)][8 halfs]
//   lane's 8 halfs (uint4) = a0,a1,a2,a3 regs of m16n8k16:
//   (r,c2),(r,c2+1) | (r+8,c2),(r+8,c2+1) | (r,c2+8),(r,c2+9) | (r+8,c2+8),(r+8,c2+9)
//   with r=lane>>2, c2=(lane&3)*2, k base = kstep*16
__device__ __half g_xs[(size_t)M_DIM * K_DIM];
// B fragment-major: [nblock(43)][kchunk(128)][ n8block(32) ][lane(32)][8 halfs]
//   lane's 8 halfs (uint4) = {ks0:b0,b1 | ks1:b0,b1}, col n = n8*8 + (lane>>2):
//   (k=c2,n),(c2+1,n) | (c2+8,n),(c2+9,n) | (16+c2,n),(16+c2+1,n) | (16+c2+8,n),(16+c2+9,n)
__device__ __half g_w[(size_t)N_DIM * K_DIM];
__device__ float g_c[M_DIM];            // c[m] = sum_k x[m,k]*s[g]*zp[g]

// ---------------- PTX helpers (generic features only; nothing needs sm_103a) ----------------
__device__ __forceinline__ uint32_t smem_u32(const void* p) {
    uint32_t a;
    asm("{ .reg .u64 t; cvta.to.shared.u64 t, %1; cvt.u32.u64 %0, t; }" : "=r"(a) : "l"(p));
    return a;
}

#define MBAR_INIT(addr, cnt) \
    asm volatile("mbarrier.init.shared.b64 [%0], %1;" :: "r"(addr), "r"((uint32_t)(cnt)) : "memory")
#define MBAR_EXPECT_TX(addr, bytes) \
    asm volatile("mbarrier.arrive.expect_tx.shared.b64 _, [%0], %1;" :: "r"(addr), "r"((uint32_t)(bytes)) : "memory")
#define MBAR_ARRIVE(addr) \
    asm volatile("mbarrier.arrive.shared.b64 _, [%0];" :: "r"(addr) : "memory")

#define MBAR_WAIT(addr, parity) do {                                              \
    uint32_t _m = (addr); uint32_t _p = (parity); uint32_t _done;                 \
    asm volatile("{ .reg .pred p;"                                                \
        " mbarrier.try_wait.parity.shared.b64 p, [%1], %2;"                       \
        " selp.b32 %0, 1, 0, p; }" : "=r"(_done) : "r"(_m), "r"(_p) : "memory");  \
    if (!_done) {                                                                 \
        asm volatile("{ .reg .pred P1;"                                           \
            " WL_%=:"                                                             \
            " mbarrier.try_wait.parity.shared.b64 P1, [%0], %1;"                  \
            " @P1 bra.uni WD_%=;"                                                 \
            " bra.uni WL_%=;"                                                     \
            " WD_%=: }" :: "r"(_m), "r"(_p) : "memory");                          \
    }                                                                             \
} while (0)

#define BULK_G2S(dst, src, bytes, mbar)                                           \
    asm volatile("cp.async.bulk.shared::cluster.global.mbarrier::complete_tx::bytes " \
                 "[%0], [%1], %2, [%3];"                                          \
                 :: "r"(dst), "l"(src), "r"((uint32_t)(bytes)), "r"(mbar) : "memory")

// fp16 mma with fp32 accumulate (sm_70+ generic)
#define MMA_F16(acc, au, b0, b1)                                                  \
    asm volatile("mma.sync.aligned.m16n8k16.row.col.f32.f16.f16.f32 "             \
        "{%0,%1,%2,%3}, {%4,%5,%6,%7}, {%8,%9}, {%0,%1,%2,%3};"                   \
        : "+f"((acc)[0]), "+f"((acc)[1]), "+f"((acc)[2]), "+f"((acc)[3])          \
        : "r"((au)[0]), "r"((au)[1]), "r"((au)[2]), "r"((au)[3]),                 \
          "r"(b0), "r"(b1))

__device__ __forceinline__ uint32_t h2u(float lo, float hi) {
    __half2 h = __floats2half2_rn(lo, hi);
    return *reinterpret_cast<uint32_t*>(&h);
}

// ---------------- prep: c[m] = sum_k x[m,k] * s[k/64] * zp[k/64] ----------------
__global__ void __launch_bounds__(256) prep_c_kernel(const float* __restrict__ x,
                                                     const float* __restrict__ scales,
                                                     const float* __restrict__ zps) {
    const int m = blockIdx.x;
    const int tid = threadIdx.x;
    const float4* xr = reinterpret_cast<const float4*>(x + (size_t)m * K_DIM);
    float acc = 0.f;
#pragma unroll
    for (int i = 0; i < 4; i++) {
        int v4 = tid + i * 256;            // float4 index 0..1023
        int g = v4 >> 4;
        float zs = scales[g] * zps[g];
        float4 v = xr[v4];
        acc += (v.x + v.y + v.z + v.w) * zs;
    }
    __shared__ float red[256];
    red[tid] = acc;
    __syncthreads();
    for (int s = 128; s > 0; s >>= 1) {
        if (tid < s) red[tid] += red[tid + s];
        __syncthreads();
    }
    if (tid == 0) g_c[m] = red[0];
}

// ---------------- prep: x' = fp16(x * s) into fragment-major layout ----------------
__global__ void __launch_bounds__(256) prep_x_kernel(const float* __restrict__ x,
                                                     const float* __restrict__ scales) {
    const int kc = blockIdx.x;             // kchunk 0..127
    const int mb = blockIdx.y;             // mblock 0..31
    const int tid = threadIdx.x;
    __shared__ float sm[TILE_M * TILE_K];  // [row][col] 128x32 floats

    const float s = scales[kc >> 1];       // group = 64 elems = 2 kchunks
    const float* xsrc = x + (size_t)mb * 128 * K_DIM + kc * 32;
#pragma unroll
    for (int i = 0; i < 16; i++) {
        int idx = tid + i * 256;
        int row = idx >> 5, col = idx & 31;
        sm[idx] = xsrc[(size_t)row * K_DIM + col] * s;
    }
    __syncthreads();

    const int lane = tid & 31, w = tid >> 5;
    uint4* dst = reinterpret_cast<uint4*>(g_xs + ((size_t)mb * K_ITERS + kc) * A_CHUNK_HALFS);
    const int r = lane >> 2, c2 = (lane & 3) * 2;
#pragma unroll
    for (int i = 0; i < 2; i++) {
        int bi = w * 2 + i;                // 0..15: (mtile*2 + kstep)
        int mt = bi >> 1, ks = bi & 1;
        int rr = mt * 16 + r;
        int k0 = ks * 16 + c2;
        uint4 v;
        v.x = h2u(sm[rr * 32 + k0],           sm[rr * 32 + k0 + 1]);
        v.y = h2u(sm[(rr + 8) * 32 + k0],     sm[(rr + 8) * 32 + k0 + 1]);
        v.z = h2u(sm[rr * 32 + k0 + 8],       sm[rr * 32 + k0 + 9]);
        v.w = h2u(sm[(rr + 8) * 32 + k0 + 8], sm[(rr + 8) * 32 + k0 + 9]);
        dst[bi * 32 + lane] = v;
    }
}

// ---------------- prep: int4 -> fp16 (exact) into fragment-major layout ----------------
__global__ void __launch_bounds__(256) prep_w_kernel(const int* __restrict__ pw) {
    const int kc = blockIdx.x;             // kchunk 0..127
    const int nb = blockIdx.y;             // nblock 0..42
    const int tid = threadIdx.x;
    __shared__ float sm[TILE_N * TILE_K];  // [n][k] 256x32 floats

    const int* src = pw + (size_t)nb * 256 * (K_DIM / 2) + kc * 16;
#pragma unroll
    for (int i = 0; i < 16; i++) {
        int idx = tid + i * 256;           // int32 index
        int n = idx >> 4, jj = idx & 15;
        int b = src[(size_t)n * (K_DIM / 2) + jj] & 255;
        sm[n * 32 + jj * 2]     = (float)(((b & 15) ^ 8) - 8);
        sm[n * 32 + jj * 2 + 1] = (float)((((b >> 4) & 15) ^ 8) - 8);
    }
    __syncthreads();

    const int lane = tid & 31, w = tid >> 5;
    uint4* dst = reinterpret_cast<uint4*>(g_w + ((size_t)nb * K_ITERS + kc) * B_CHUNK_HALFS);
    const int nr = (lane >> 2), c2 = (lane & 3) * 2;
#pragma unroll
    for (int i = 0; i < 4; i++) {
        int p = w * 4 + i;                 // n8 block 0..31
        int n = p * 8 + nr;
        uint4 v;
        v.x = h2u(sm[n * 32 + c2],      sm[n * 32 + c2 + 1]);       // ks0 b0
        v.y = h2u(sm[n * 32 + c2 + 8],  sm[n * 32 + c2 + 9]);       // ks0 b1
        v.z = h2u(sm[n * 32 + 16 + c2], sm[n * 32 + 16 + c2 + 1]);  // ks1 b0
        v.w = h2u(sm[n * 32 + 24 + c2], sm[n * 32 + 24 + c2 + 1]);  // ks1 b1
        dst[p * 32 + lane] = v;
    }
}

// ---------------- GEMM: out = x' @ w4^T + (bias - c) ----------------
__global__ void __launch_bounds__(512, 1) gemm_kernel(const float* __restrict__ bias,
                                                      float* __restrict__ out) {
    extern __shared__ char smem[];
    const uint32_t sb = smem_u32(smem);
    const int tid = threadIdx.x;
    const int lane = tid & 31;
    const int wid = tid >> 5;
    const int wm = wid >> 2;               // 0..3
    const int wn = wid & 3;                // 0..3

    const int bid = blockIdx.x;
    const int nb = bid / M_TILES;          // m fastest: consecutive CTAs share B panel
    const int mb = bid % M_TILES;

    const __half* gA = g_xs + (size_t)mb * K_ITERS * A_CHUNK_HALFS;
    const __half* gB = g_w + (size_t)nb * K_ITERS * B_CHUNK_HALFS;

    if (tid == 0) {
#pragma unroll
        for (int s = 0; s < STAGES; s++) {
            MBAR_INIT(sb + SM_FULL + 8 * s, 1);
            MBAR_INIT(sb + SM_EMPTY + 8 * s, 16);
        }
        asm volatile("fence.mbarrier_init.release.cluster;" ::: "memory");
    }
    __syncthreads();

    if (tid == 0) {
#pragma unroll
        for (int s = 0; s < STAGES; s++) {
            MBAR_EXPECT_TX(sb + SM_FULL + 8 * s, CHUNK_BYTES);
            BULK_G2S(sb + SM_A + s * A_STAGE_BYTES, gA + (size_t)s * A_CHUNK_HALFS, A_STAGE_BYTES, sb + SM_FULL + 8 * s);
            BULK_G2S(sb + SM_B + s * B_STAGE_BYTES, gB + (size_t)s * B_CHUNK_HALFS, B_STAGE_BYTES, sb + SM_FULL + 8 * s);
        }
    }

    float acc[2][8][4];
#pragma unroll
    for (int a = 0; a < 2; a++)
#pragma unroll
        for (int b = 0; b < 8; b++)
#pragma unroll
            for (int d = 0; d < 4; d++) acc[a][b][d] = 0.f;

    int ph = 0;

    for (int itb = 0; itb < K_ITERS / STAGES; itb++) {
#pragma unroll
        for (int s = 0; s < STAGES; s++) {
            const int it = itb * STAGES + s;
            MBAR_WAIT(sb + SM_FULL + 8 * s, ph);

            const uint4* As = reinterpret_cast<const uint4*>(smem + SM_A + s * A_STAGE_BYTES);
            const uint4* Bs = reinterpret_cast<const uint4*>(smem + SM_B + s * B_STAGE_BYTES);

            // A frags: [mt][ks] each uint4 = a0..a3
            uint4 af[2][2];
#pragma unroll
            for (int mt = 0; mt < 2; mt++)
#pragma unroll
                for (int ks = 0; ks < 2; ks++)
                    af[mt][ks] = As[((wm * 2 + mt) * 2 + ks) * 32 + lane];

#pragma unroll
            for (int j = 0; j < 8; j++) {
                uint4 bj = Bs[(wn * 8 + j) * 32 + lane];
#pragma unroll
                for (int mt = 0; mt < 2; mt++) {
                    const uint32_t* a0 = reinterpret_cast<const uint32_t*>(&af[mt][0]);
                    const uint32_t* a1 = reinterpret_cast<const uint32_t*>(&af[mt][1]);
                    MMA_F16(acc[mt][j], a0, bj.x, bj.y);
                    MMA_F16(acc[mt][j], a1, bj.z, bj.w);
                }
            }
            __syncwarp();
            if (lane == 0) MBAR_ARRIVE(sb + SM_EMPTY + 8 * s);

            if (tid == 0 && it + STAGES < K_ITERS) {
                MBAR_WAIT(sb + SM_EMPTY + 8 * s, ph);
                MBAR_EXPECT_TX(sb + SM_FULL + 8 * s, CHUNK_BYTES);
                BULK_G2S(sb + SM_A + s * A_STAGE_BYTES, gA + (size_t)(it + STAGES) * A_CHUNK_HALFS, A_STAGE_BYTES, sb + SM_FULL + 8 * s);
                BULK_G2S(sb + SM_B + s * B_STAGE_BYTES, gB + (size_t)(it + STAGES) * B_CHUNK_HALFS, B_STAGE_BYTES, sb + SM_FULL + 8 * s);
            }
        }
        ph ^= 1;
    }

    // ---- epilogue: out = acc + bias[n] - c[m] ----
    const int c0 = (lane & 3) * 2;
    const int r0 = lane >> 2;
    const int ncol = nb * 256 + wn * 64 + c0;
    float2 bv[8];
#pragma unroll
    for (int j = 0; j < 8; j++) bv[j] = *reinterpret_cast<const float2*>(bias + ncol + j * 8);

    const int mrow = mb * 128 + wm * 32 + r0;
    float cm[4];
#pragma unroll
    for (int i = 0; i < 4; i++) cm[i] = g_c[mrow + i * 8];

#pragma unroll
    for (int mt = 0; mt < 2; mt++) {
#pragma unroll
        for (int h = 0; h < 2; h++) {
            const float cmv = cm[mt * 2 + h];
            float* orow = out + (size_t)(mrow + mt * 16 + h * 8) * N_DIM + ncol;
#pragma unroll
            for (int j = 0; j < 8; j++) {
                float2 v;
                v.x = acc[mt][j][h * 2 + 0] + bv[j].x - cmv;
                v.y = acc[mt][j][h * 2 + 1] + bv[j].y - cmv;
                *reinterpret_cast<float2*>(orow + j * 8) = v;
            }
        }
    }
}

// ---------------- host ----------------
extern "C" void kernel_launch(void* const* d_in, const int* in_sizes, int n_in,
                              void* d_out, int out_size) {
    const float* x      = (const float*)d_in[0];
    const int*   pw     = (const int*)d_in[1];
    const float* scales = (const float*)d_in[2];
    const float* zps    = (const float*)d_in[3];
    const float* bias   = (const float*)d_in[4];
    float* out = (float*)d_out;

    cudaFuncSetAttribute(gemm_kernel, cudaFuncAttributeMaxDynamicSharedMemorySize, SMEM_BYTES);

    prep_c_kernel<<<M_DIM, 256>>>(x, scales, zps);
    prep_x_kernel<<<dim3(K_ITERS, M_TILES), 256>>>(x, scales);
    prep_w_kernel<<<dim3(K_ITERS, N_TILES), 256>>>(pw);
    gemm_kernel<<<M_TILES * N_TILES, 512, SMEM_BYTES>>>(bias, out);
}

// round 7
// speedup vs baseline: 1.8665x; 1.0796x over previous
#include <cuda_runtime.h>
#include <cuda_fp16.h>
#include <cstdint>

// ---------------- problem dims ----------------
#define M_DIM 4096
#define K_DIM 4096
#define N_DIM 11008

#define TILE_M 128
#define TILE_N 256
#define TILE_K 64
#define STAGES 4
#define K_CHUNKS (K_DIM / TILE_K)      // 64
#define M_TILES (M_DIM / TILE_M)       // 32
#define N_TILES (N_DIM / TILE_N)       // 43

#define A_CHUNK_HALFS (TILE_M * TILE_K)       // 8192
#define B_CHUNK_HALFS (TILE_N * TILE_K)       // 16384
#define A_STAGE_BYTES (A_CHUNK_HALFS * 2)     // 16384
#define B_STAGE_BYTES (B_CHUNK_HALFS * 2)     // 32768
#define CHUNK_BYTES   (A_STAGE_BYTES + B_STAGE_BYTES)

#define SM_FULL  64
#define SM_EMPTY 128
#define SM_A     1024
#define SM_B     (SM_A + STAGES * A_STAGE_BYTES)       // 66560
#define SMEM_BYTES (SM_B + STAGES * B_STAGE_BYTES)     // 197632

// ---------------- scratch (device globals; allocation forbidden) ----------------
// A fragment-major: [mblock(32)][kchunk64(64)][bi(32)][lane(32)] uint4
//   bi = mtile(0..7)*4 + kstep(0..3); kstep = 16-k slice within the 64-k chunk.
//   lane's uint4 = a0..a3 of m16n8k16 (r=lane>>2, c2=(lane&3)*2):
//   (r,c2),(r,c2+1) | (r+8,c2),(r+8,c2+1) | (r,c2+8),(r,c2+9) | (r+8,c2+8),(r+8,c2+9)
__device__ __half g_xs[(size_t)M_DIM * K_DIM];
// B fragment-major: [nblock(43)][kchunk64(64)][p(32)*2 + kh(2)][lane(32)] uint4
//   p = n8 block; kh selects ksteps {2kh, 2kh+1}; lane's uint4 =
//   {ks(2kh): b0,b1 | ks(2kh+1): b0,b1}, col n = p*8 + (lane>>2)
__device__ __half g_w[(size_t)N_DIM * K_DIM];
__device__ float g_c[M_DIM];            // c[m] = sum_k x[m,k]*s[g]*zp[g]

// ---------------- PTX helpers (generic features only) ----------------
__device__ __forceinline__ uint32_t smem_u32(const void* p) {
    uint32_t a;
    asm("{ .reg .u64 t; cvta.to.shared.u64 t, %1; cvt.u32.u64 %0, t; }" : "=r"(a) : "l"(p));
    return a;
}

#define MBAR_INIT(addr, cnt) \
    asm volatile("mbarrier.init.shared.b64 [%0], %1;" :: "r"(addr), "r"((uint32_t)(cnt)) : "memory")
#define MBAR_EXPECT_TX(addr, bytes) \
    asm volatile("mbarrier.arrive.expect_tx.shared.b64 _, [%0], %1;" :: "r"(addr), "r"((uint32_t)(bytes)) : "memory")
#define MBAR_ARRIVE(addr) \
    asm volatile("mbarrier.arrive.shared.b64 _, [%0];" :: "r"(addr) : "memory")

#define MBAR_WAIT(addr, parity) do {                                              \
    uint32_t _m = (addr); uint32_t _p = (parity); uint32_t _done;                 \
    asm volatile("{ .reg .pred p;"                                                \
        " mbarrier.try_wait.parity.shared.b64 p, [%1], %2;"                       \
        " selp.b32 %0, 1, 0, p; }" : "=r"(_done) : "r"(_m), "r"(_p) : "memory");  \
    if (!_done) {                                                                 \
        asm volatile("{ .reg .pred P1;"                                           \
            " WL_%=:"                                                             \
            " mbarrier.try_wait.parity.shared.b64 P1, [%0], %1;"                  \
            " @P1 bra.uni WD_%=;"                                                 \
            " bra.uni WL_%=;"                                                     \
            " WD_%=: }" :: "r"(_m), "r"(_p) : "memory");                          \
    }                                                                             \
} while (0)

#define BULK_G2S(dst, src, bytes, mbar)                                           \
    asm volatile("cp.async.bulk.shared::cluster.global.mbarrier::complete_tx::bytes " \
                 "[%0], [%1], %2, [%3];"                                          \
                 :: "r"(dst), "l"(src), "r"((uint32_t)(bytes)), "r"(mbar) : "memory")

#define MMA_F16(acc, au, b0, b1)                                                  \
    asm volatile("mma.sync.aligned.m16n8k16.row.col.f32.f16.f16.f32 "             \
        "{%0,%1,%2,%3}, {%4,%5,%6,%7}, {%8,%9}, {%0,%1,%2,%3};"                   \
        : "+f"((acc)[0]), "+f"((acc)[1]), "+f"((acc)[2]), "+f"((acc)[3])          \
        : "r"((au)[0]), "r"((au)[1]), "r"((au)[2]), "r"((au)[3]),                 \
          "r"(b0), "r"(b1))

__device__ __forceinline__ uint32_t h2u(float lo, float hi) {
    __half2 h = __floats2half2_rn(lo, hi);
    return *reinterpret_cast<uint32_t*>(&h);
}

// ---------------- prep: c[m] = sum_k x[m,k] * s[k/64] * zp[k/64] ----------------
__global__ void __launch_bounds__(256) prep_c_kernel(const float* __restrict__ x,
                                                     const float* __restrict__ scales,
                                                     const float* __restrict__ zps) {
    const int m = blockIdx.x;
    const int tid = threadIdx.x;
    const float4* xr = reinterpret_cast<const float4*>(x + (size_t)m * K_DIM);
    float acc = 0.f;
#pragma unroll
    for (int i = 0; i < 4; i++) {
        int v4 = tid + i * 256;
        int g = v4 >> 4;
        float zs = scales[g] * zps[g];
        float4 v = xr[v4];
        acc += (v.x + v.y + v.z + v.w) * zs;
    }
    __shared__ float red[256];
    red[tid] = acc;
    __syncthreads();
    for (int s = 128; s > 0; s >>= 1) {
        if (tid < s) red[tid] += red[tid + s];
        __syncthreads();
    }
    if (tid == 0) g_c[m] = red[0];
}

// ---------------- prep: x' = fp16(x * s) into fragment-major layout ----------------
// grid (kc32 0..127, mb 0..31); writes into the kc32's half of the 64-k chunk
__global__ void __launch_bounds__(256) prep_x_kernel(const float* __restrict__ x,
                                                     const float* __restrict__ scales) {
    const int kc = blockIdx.x;             // 32-k granule 0..127
    const int mb = blockIdx.y;
    const int tid = threadIdx.x;
    __shared__ float sm[TILE_M * 32];      // 128x32 floats

    const float s = scales[kc >> 1];       // group = 64 elems = 2 granules
    const float* xsrc = x + (size_t)mb * 128 * K_DIM + kc * 32;
#pragma unroll
    for (int i = 0; i < 16; i++) {
        int idx = tid + i * 256;
        int row = idx >> 5, col = idx & 31;
        sm[idx] = xsrc[(size_t)row * K_DIM + col] * s;
    }
    __syncthreads();

    const int lane = tid & 31, w = tid >> 5;
    uint4* dst = reinterpret_cast<uint4*>(
        g_xs + ((size_t)mb * K_CHUNKS + (kc >> 1)) * A_CHUNK_HALFS);
    const int r = lane >> 2, c2 = (lane & 3) * 2;
    const int khalf = (kc & 1) * 2;        // kstep offset within chunk
#pragma unroll
    for (int i = 0; i < 2; i++) {
        int blk = w * 2 + i;               // 0..15
        int mt = blk >> 1, ks = blk & 1;   // local kstep 0..1
        int rr = mt * 16 + r;
        int k0 = ks * 16 + c2;
        uint4 v;
        v.x = h2u(sm[rr * 32 + k0],           sm[rr * 32 + k0 + 1]);
        v.y = h2u(sm[(rr + 8) * 32 + k0],     sm[(rr + 8) * 32 + k0 + 1]);
        v.z = h2u(sm[rr * 32 + k0 + 8],       sm[rr * 32 + k0 + 9]);
        v.w = h2u(sm[(rr + 8) * 32 + k0 + 8], sm[(rr + 8) * 32 + k0 + 9]);
        dst[(mt * 4 + khalf + ks) * 32 + lane] = v;
    }
}

// ---------------- prep: int4 -> fp16 (exact) into fragment-major layout ----------------
__global__ void __launch_bounds__(256) prep_w_kernel(const int* __restrict__ pw) {
    const int kc = blockIdx.x;             // 32-k granule 0..127
    const int nb = blockIdx.y;
    const int tid = threadIdx.x;
    __shared__ float sm[TILE_N * 32];      // 256x32 floats

    const int* src = pw + (size_t)nb * 256 * (K_DIM / 2) + kc * 16;
#pragma unroll
    for (int i = 0; i < 16; i++) {
        int idx = tid + i * 256;
        int n = idx >> 4, jj = idx & 15;
        int b = src[(size_t)n * (K_DIM / 2) + jj] & 255;
        sm[n * 32 + jj * 2]     = (float)(((b & 15) ^ 8) - 8);
        sm[n * 32 + jj * 2 + 1] = (float)((((b >> 4) & 15) ^ 8) - 8);
    }
    __syncthreads();

    const int lane = tid & 31, w = tid >> 5;
    uint4* dst = reinterpret_cast<uint4*>(
        g_w + ((size_t)nb * K_CHUNKS + (kc >> 1)) * B_CHUNK_HALFS);
    const int nr = (lane >> 2), c2 = (lane & 3) * 2;
    const int kh = kc & 1;                 // which uint4 of the pair
#pragma unroll
    for (int i = 0; i < 4; i++) {
        int p = w * 4 + i;                 // n8 block 0..31
        int n = p * 8 + nr;
        uint4 v;
        v.x = h2u(sm[n * 32 + c2],      sm[n * 32 + c2 + 1]);
        v.y = h2u(sm[n * 32 + c2 + 8],  sm[n * 32 + c2 + 9]);
        v.z = h2u(sm[n * 32 + 16 + c2], sm[n * 32 + 16 + c2 + 1]);
        v.w = h2u(sm[n * 32 + 24 + c2], sm[n * 32 + 24 + c2 + 1]);
        dst[(p * 2 + kh) * 32 + lane] = v;
    }
}

// ---------------- GEMM: out = x' @ w4^T + (bias - c) ----------------
__global__ void __launch_bounds__(512, 1) gemm_kernel(const float* __restrict__ bias,
                                                      float* __restrict__ out) {
    extern __shared__ char smem[];
    const uint32_t sb = smem_u32(smem);
    const int tid = threadIdx.x;
    const int lane = tid & 31;
    const int wid = tid >> 5;
    const int wm = wid >> 2;               // 0..3
    const int wn = wid & 3;                // 0..3

    const int bid = blockIdx.x;
    const int nb = bid / M_TILES;          // m fastest: consecutive CTAs share B panel
    const int mb = bid % M_TILES;

    const __half* gA = g_xs + (size_t)mb * K_CHUNKS * A_CHUNK_HALFS;
    const __half* gB = g_w + (size_t)nb * K_CHUNKS * B_CHUNK_HALFS;

    if (tid == 0) {
#pragma unroll
        for (int s = 0; s < STAGES; s++) {
            MBAR_INIT(sb + SM_FULL + 8 * s, 1);
            MBAR_INIT(sb + SM_EMPTY + 8 * s, 16);
        }
        asm volatile("fence.mbarrier_init.release.cluster;" ::: "memory");
    }
    __syncthreads();

    // initial fill: stage s owned by warp s, lane 0 (one owner per SMSP)
    if (wid < STAGES && lane == 0) {
        const int s = wid;
        MBAR_EXPECT_TX(sb + SM_FULL + 8 * s, CHUNK_BYTES);
        BULK_G2S(sb + SM_A + s * A_STAGE_BYTES, gA + (size_t)s * A_CHUNK_HALFS, A_STAGE_BYTES, sb + SM_FULL + 8 * s);
        BULK_G2S(sb + SM_B + s * B_STAGE_BYTES, gB + (size_t)s * B_CHUNK_HALFS, B_STAGE_BYTES, sb + SM_FULL + 8 * s);
    }

    float acc[2][8][4];
#pragma unroll
    for (int a = 0; a < 2; a++)
#pragma unroll
        for (int b = 0; b < 8; b++)
#pragma unroll
            for (int d = 0; d < 4; d++) acc[a][b][d] = 0.f;

#pragma unroll 4
    for (int it = 0; it < K_CHUNKS; ++it) {
        const int s = it & (STAGES - 1);
        const int ph = (it >> 2) & 1;
        MBAR_WAIT(sb + SM_FULL + 8 * s, ph);

        const uint4* As = reinterpret_cast<const uint4*>(smem + SM_A + s * A_STAGE_BYTES);
        const uint4* Bs = reinterpret_cast<const uint4*>(smem + SM_B + s * B_STAGE_BYTES);

        // A frags: [mt][ks] (2 x 4 uint4)
        uint4 af[2][4];
#pragma unroll
        for (int mt = 0; mt < 2; mt++)
#pragma unroll
            for (int ks = 0; ks < 4; ks++)
                af[mt][ks] = As[((wm * 2 + mt) * 4 + ks) * 32 + lane];

#pragma unroll
        for (int j = 0; j < 8; j++) {
            const int p = wn * 8 + j;
            uint4 b0 = Bs[(p * 2 + 0) * 32 + lane];   // ksteps 0,1
            uint4 b1 = Bs[(p * 2 + 1) * 32 + lane];   // ksteps 2,3
#pragma unroll
            for (int mt = 0; mt < 2; mt++) {
                MMA_F16(acc[mt][j], reinterpret_cast<const uint32_t*>(&af[mt][0]), b0.x, b0.y);
                MMA_F16(acc[mt][j], reinterpret_cast<const uint32_t*>(&af[mt][1]), b0.z, b0.w);
                MMA_F16(acc[mt][j], reinterpret_cast<const uint32_t*>(&af[mt][2]), b1.x, b1.y);
                MMA_F16(acc[mt][j], reinterpret_cast<const uint32_t*>(&af[mt][3]), b1.z, b1.w);
            }
        }
        __syncwarp();
        if (lane == 0) MBAR_ARRIVE(sb + SM_EMPTY + 8 * s);

        // distributed refill: owner of stage s refills chunk it+STAGES
        if (wid == s && lane == 0 && it + STAGES < K_CHUNKS) {
            MBAR_WAIT(sb + SM_EMPTY + 8 * s, ph);
            MBAR_EXPECT_TX(sb + SM_FULL + 8 * s, CHUNK_BYTES);
            BULK_G2S(sb + SM_A + s * A_STAGE_BYTES, gA + (size_t)(it + STAGES) * A_CHUNK_HALFS, A_STAGE_BYTES, sb + SM_FULL + 8 * s);
            BULK_G2S(sb + SM_B + s * B_STAGE_BYTES, gB + (size_t)(it + STAGES) * B_CHUNK_HALFS, B_STAGE_BYTES, sb + SM_FULL + 8 * s);
        }
    }

    // ---- epilogue: out = acc + bias[n] - c[m] ----
    const int c0 = (lane & 3) * 2;
    const int r0 = lane >> 2;
    const int ncol = nb * 256 + wn * 64 + c0;
    float2 bv[8];
#pragma unroll
    for (int j = 0; j < 8; j++) bv[j] = *reinterpret_cast<const float2*>(bias + ncol + j * 8);

    const int mrow = mb * 128 + wm * 32 + r0;
    float cm[4];
#pragma unroll
    for (int i = 0; i < 4; i++) cm[i] = g_c[mrow + i * 8];

#pragma unroll
    for (int mt = 0; mt < 2; mt++) {
#pragma unroll
        for (int h = 0; h < 2; h++) {
            const float cmv = cm[mt * 2 + h];
            float* orow = out + (size_t)(mrow + mt * 16 + h * 8) * N_DIM + ncol;
#pragma unroll
            for (int j = 0; j < 8; j++) {
                float2 v;
                v.x = acc[mt][j][h * 2 + 0] + bv[j].x - cmv;
                v.y = acc[mt][j][h * 2 + 1] + bv[j].y - cmv;
                *reinterpret_cast<float2*>(orow + j * 8) = v;
            }
        }
    }
}

// ---------------- host ----------------
extern "C" void kernel_launch(void* const* d_in, const int* in_sizes, int n_in,
                              void* d_out, int out_size) {
    const float* x      = (const float*)d_in[0];
    const int*   pw     = (const int*)d_in[1];
    const float* scales = (const float*)d_in[2];
    const float* zps    = (const float*)d_in[3];
    const float* bias   = (const float*)d_in[4];
    float* out = (float*)d_out;

    cudaFuncSetAttribute(gemm_kernel, cudaFuncAttributeMaxDynamicSharedMemorySize, SMEM_BYTES);

    prep_c_kernel<<<M_DIM, 256>>>(x, scales, zps);
    prep_x_kernel<<<dim3(128, M_TILES), 256>>>(x, scales);
    prep_w_kernel<<<dim3(128, N_TILES), 256>>>(pw);
    gemm_kernel<<<M_TILES * N_TILES, 512, SMEM_BYTES>>>(bias, out);
}

// round 8
// speedup vs baseline: 1.9531x; 1.0464x over previous
#include <cuda_runtime.h>
#include <cuda_fp16.h>
#include <cstdint>

// ---------------- problem dims ----------------
#define M_DIM 4096
#define K_DIM 4096
#define N_DIM 11008

#define TILE_M 128
#define TILE_N 128
#define TILE_K 64
#define STAGES 3
#define K_CHUNKS (K_DIM / TILE_K)      // 64
#define M_TILES (M_DIM / TILE_M)       // 32
#define N_TILES (N_DIM / TILE_N)       // 86

#define A_CHUNK_HALFS (TILE_M * TILE_K)       // 8192
#define B_CHUNK_HALFS (TILE_N * TILE_K)       // 8192
#define A_STAGE_BYTES (A_CHUNK_HALFS * 2)     // 16384
#define B_STAGE_BYTES (B_CHUNK_HALFS * 2)     // 16384
#define CHUNK_BYTES   (A_STAGE_BYTES + B_STAGE_BYTES)

#define SM_FULL  64
#define SM_EMPTY 128
#define SM_A     1024
#define SM_B     (SM_A + STAGES * A_STAGE_BYTES)       // 50176
#define SMEM_BYTES (SM_B + STAGES * B_STAGE_BYTES)     // 99328  (x2 CTAs = 198656)

// ---------------- scratch (device globals; allocation forbidden) ----------------
// A fragment-major: [mblock(32)][kchunk64(64)][bi(32)][lane(32)] uint4
//   bi = mtile(0..7)*4 + kstep(0..3).  lane's uint4 = a0..a3 of m16n8k16
//   (r=lane>>2, c2=(lane&3)*2):
//   (r,c2),(r,c2+1) | (r+8,c2),(r+8,c2+1) | (r,c2+8),(r,c2+9) | (r+8,c2+8),(r+8,c2+9)
__device__ __half g_xs[(size_t)M_DIM * K_DIM];
// B fragment-major: [nblock(86)][kchunk64(64)][p(16)*2 + kh(2)][lane(32)] uint4
//   p = n8 block (0..15); kh selects ksteps {2kh, 2kh+1}; lane's uint4 =
//   {ks(2kh): b0,b1 | ks(2kh+1): b0,b1}, col n = p*8 + (lane>>2)
__device__ __half g_w[(size_t)N_DIM * K_DIM];
__device__ float g_c[M_DIM];            // c[m] = sum_k x[m,k]*s[g]*zp[g]

// ---------------- PTX helpers (generic features only) ----------------
__device__ __forceinline__ uint32_t smem_u32(const void* p) {
    uint32_t a;
    asm("{ .reg .u64 t; cvta.to.shared.u64 t, %1; cvt.u32.u64 %0, t; }" : "=r"(a) : "l"(p));
    return a;
}

#define MBAR_INIT(addr, cnt) \
    asm volatile("mbarrier.init.shared.b64 [%0], %1;" :: "r"(addr), "r"((uint32_t)(cnt)) : "memory")
#define MBAR_EXPECT_TX(addr, bytes) \
    asm volatile("mbarrier.arrive.expect_tx.shared.b64 _, [%0], %1;" :: "r"(addr), "r"((uint32_t)(bytes)) : "memory")
#define MBAR_ARRIVE(addr) \
    asm volatile("mbarrier.arrive.shared.b64 _, [%0];" :: "r"(addr) : "memory")

#define MBAR_WAIT(addr, parity) do {                                              \
    uint32_t _m = (addr); uint32_t _p = (parity); uint32_t _done;                 \
    asm volatile("{ .reg .pred p;"                                                \
        " mbarrier.try_wait.parity.shared.b64 p, [%1], %2;"                       \
        " selp.b32 %0, 1, 0, p; }" : "=r"(_done) : "r"(_m), "r"(_p) : "memory");  \
    if (!_done) {                                                                 \
        asm volatile("{ .reg .pred P1;"                                           \
            " WL_%=:"                                                             \
            " mbarrier.try_wait.parity.shared.b64 P1, [%0], %1;"                  \
            " @P1 bra.uni WD_%=;"                                                 \
            " bra.uni WL_%=;"                                                     \
            " WD_%=: }" :: "r"(_m), "r"(_p) : "memory");                          \
    }                                                                             \
} while (0)

#define BULK_G2S(dst, src, bytes, mbar)                                           \
    asm volatile("cp.async.bulk.shared::cluster.global.mbarrier::complete_tx::bytes " \
                 "[%0], [%1], %2, [%3];"                                          \
                 :: "r"(dst), "l"(src), "r"((uint32_t)(bytes)), "r"(mbar) : "memory")

#define MMA_F16(acc, au, b0, b1)                                                  \
    asm volatile("mma.sync.aligned.m16n8k16.row.col.f32.f16.f16.f32 "             \
        "{%0,%1,%2,%3}, {%4,%5,%6,%7}, {%8,%9}, {%0,%1,%2,%3};"                   \
        : "+f"((acc)[0]), "+f"((acc)[1]), "+f"((acc)[2]), "+f"((acc)[3])          \
        : "r"((au)[0]), "r"((au)[1]), "r"((au)[2]), "r"((au)[3]),                 \
          "r"(b0), "r"(b1))

__device__ __forceinline__ uint32_t h2u(float lo, float hi) {
    __half2 h = __floats2half2_rn(lo, hi);
    return *reinterpret_cast<uint32_t*>(&h);
}

// ---------------- prep: c[m] = sum_k x[m,k] * s[k/64] * zp[k/64] ----------------
__global__ void __launch_bounds__(256) prep_c_kernel(const float* __restrict__ x,
                                                     const float* __restrict__ scales,
                                                     const float* __restrict__ zps) {
    const int m = blockIdx.x;
    const int tid = threadIdx.x;
    const float4* xr = reinterpret_cast<const float4*>(x + (size_t)m * K_DIM);
    float acc = 0.f;
#pragma unroll
    for (int i = 0; i < 4; i++) {
        int v4 = tid + i * 256;
        int g = v4 >> 4;
        float zs = scales[g] * zps[g];
        float4 v = xr[v4];
        acc += (v.x + v.y + v.z + v.w) * zs;
    }
    __shared__ float red[256];
    red[tid] = acc;
    __syncthreads();
    for (int s = 128; s > 0; s >>= 1) {
        if (tid < s) red[tid] += red[tid + s];
        __syncthreads();
    }
    if (tid == 0) g_c[m] = red[0];
}

// ---------------- prep: x' = fp16(x * s) into fragment-major layout ----------------
__global__ void __launch_bounds__(256) prep_x_kernel(const float* __restrict__ x,
                                                     const float* __restrict__ scales) {
    const int kc = blockIdx.x;             // 32-k granule 0..127
    const int mb = blockIdx.y;
    const int tid = threadIdx.x;
    __shared__ float sm[TILE_M * 32];      // 128x32 floats

    const float s = scales[kc >> 1];       // group = 64 elems = 2 granules
    const float* xsrc = x + (size_t)mb * 128 * K_DIM + kc * 32;
#pragma unroll
    for (int i = 0; i < 16; i++) {
        int idx = tid + i * 256;
        int row = idx >> 5, col = idx & 31;
        sm[idx] = xsrc[(size_t)row * K_DIM + col] * s;
    }
    __syncthreads();

    const int lane = tid & 31, w = tid >> 5;
    uint4* dst = reinterpret_cast<uint4*>(
        g_xs + ((size_t)mb * K_CHUNKS + (kc >> 1)) * A_CHUNK_HALFS);
    const int r = lane >> 2, c2 = (lane & 3) * 2;
    const int khalf = (kc & 1) * 2;        // kstep offset within 64-k chunk
#pragma unroll
    for (int i = 0; i < 2; i++) {
        int blk = w * 2 + i;               // 0..15
        int mt = blk >> 1, ks = blk & 1;
        int rr = mt * 16 + r;
        int k0 = ks * 16 + c2;
        uint4 v;
        v.x = h2u(sm[rr * 32 + k0],           sm[rr * 32 + k0 + 1]);
        v.y = h2u(sm[(rr + 8) * 32 + k0],     sm[(rr + 8) * 32 + k0 + 1]);
        v.z = h2u(sm[rr * 32 + k0 + 8],       sm[rr * 32 + k0 + 9]);
        v.w = h2u(sm[(rr + 8) * 32 + k0 + 8], sm[(rr + 8) * 32 + k0 + 9]);
        dst[(mt * 4 + khalf + ks) * 32 + lane] = v;
    }
}

// ---------------- prep: int4 -> fp16 (exact) into fragment-major layout ----------------
__global__ void __launch_bounds__(256) prep_w_kernel(const int* __restrict__ pw) {
    const int kc = blockIdx.x;             // 32-k granule 0..127
    const int nb = blockIdx.y;             // nblock 0..85 (128 rows each)
    const int tid = threadIdx.x;
    __shared__ float sm[TILE_N * 32];      // 128x32 floats

    const int* src = pw + (size_t)nb * 128 * (K_DIM / 2) + kc * 16;
#pragma unroll
    for (int i = 0; i < 8; i++) {
        int idx = tid + i * 256;           // int32 index 0..2047
        int n = idx >> 4, jj = idx & 15;
        int b = src[(size_t)n * (K_DIM / 2) + jj] & 255;
        sm[n * 32 + jj * 2]     = (float)(((b & 15) ^ 8) - 8);
        sm[n * 32 + jj * 2 + 1] = (float)((((b >> 4) & 15) ^ 8) - 8);
    }
    __syncthreads();

    const int lane = tid & 31, w = tid >> 5;
    uint4* dst = reinterpret_cast<uint4*>(
        g_w + ((size_t)nb * K_CHUNKS + (kc >> 1)) * B_CHUNK_HALFS);
    const int nr = (lane >> 2), c2 = (lane & 3) * 2;
    const int kh = kc & 1;
#pragma unroll
    for (int i = 0; i < 2; i++) {
        int p = w * 2 + i;                 // n8 block 0..15
        int n = p * 8 + nr;
        uint4 v;
        v.x = h2u(sm[n * 32 + c2],      sm[n * 32 + c2 + 1]);
        v.y = h2u(sm[n * 32 + c2 + 8],  sm[n * 32 + c2 + 9]);
        v.z = h2u(sm[n * 32 + 16 + c2], sm[n * 32 + 16 + c2 + 1]);
        v.w = h2u(sm[n * 32 + 24 + c2], sm[n * 32 + 24 + c2 + 1]);
        dst[(p * 2 + kh) * 32 + lane] = v;
    }
}

// ---------------- GEMM: out = x' @ w4^T + (bias - c) ----------------
// 256 threads, 8 warps (4 m x 2 n), 2 CTAs per SM
__global__ void __launch_bounds__(256, 2) gemm_kernel(const float* __restrict__ bias,
                                                      float* __restrict__ out) {
    extern __shared__ char smem[];
    const uint32_t sb = smem_u32(smem);
    const int tid = threadIdx.x;
    const int lane = tid & 31;
    const int wid = tid >> 5;
    const int wm = wid >> 1;               // 0..3
    const int wn = wid & 1;                // 0..1

    const int bid = blockIdx.x;
    const int nb = bid / M_TILES;          // m fastest: co-resident CTAs share B panel
    const int mb = bid % M_TILES;

    const __half* gA = g_xs + (size_t)mb * K_CHUNKS * A_CHUNK_HALFS;
    const __half* gB = g_w + (size_t)nb * K_CHUNKS * B_CHUNK_HALFS;

    if (tid == 0) {
#pragma unroll
        for (int s = 0; s < STAGES; s++) {
            MBAR_INIT(sb + SM_FULL + 8 * s, 1);
            MBAR_INIT(sb + SM_EMPTY + 8 * s, 8);
        }
        asm volatile("fence.mbarrier_init.release.cluster;" ::: "memory");
    }
    __syncthreads();

    // initial fill: stage s owned by warp s, lane 0
    if (wid < STAGES && lane == 0) {
        const int s = wid;
        MBAR_EXPECT_TX(sb + SM_FULL + 8 * s, CHUNK_BYTES);
        BULK_G2S(sb + SM_A + s * A_STAGE_BYTES, gA + (size_t)s * A_CHUNK_HALFS, A_STAGE_BYTES, sb + SM_FULL + 8 * s);
        BULK_G2S(sb + SM_B + s * B_STAGE_BYTES, gB + (size_t)s * B_CHUNK_HALFS, B_STAGE_BYTES, sb + SM_FULL + 8 * s);
    }

    float acc[2][8][4];
#pragma unroll
    for (int a = 0; a < 2; a++)
#pragma unroll
        for (int b = 0; b < 8; b++)
#pragma unroll
            for (int d = 0; d < 4; d++) acc[a][b][d] = 0.f;

    int s = 0, ph = 0;
#pragma unroll 3
    for (int it = 0; it < K_CHUNKS; ++it) {
        MBAR_WAIT(sb + SM_FULL + 8 * s, ph);

        const uint4* As = reinterpret_cast<const uint4*>(smem + SM_A + s * A_STAGE_BYTES);
        const uint4* Bs = reinterpret_cast<const uint4*>(smem + SM_B + s * B_STAGE_BYTES);

        uint4 af[2][4];
#pragma unroll
        for (int mt = 0; mt < 2; mt++)
#pragma unroll
            for (int ks = 0; ks < 4; ks++)
                af[mt][ks] = As[((wm * 2 + mt) * 4 + ks) * 32 + lane];

#pragma unroll
        for (int j = 0; j < 8; j++) {
            const int p = wn * 8 + j;
            uint4 b0 = Bs[(p * 2 + 0) * 32 + lane];   // ksteps 0,1
            uint4 b1 = Bs[(p * 2 + 1) * 32 + lane];   // ksteps 2,3
#pragma unroll
            for (int mt = 0; mt < 2; mt++) {
                MMA_F16(acc[mt][j], reinterpret_cast<const uint32_t*>(&af[mt][0]), b0.x, b0.y);
                MMA_F16(acc[mt][j], reinterpret_cast<const uint32_t*>(&af[mt][1]), b0.z, b0.w);
                MMA_F16(acc[mt][j], reinterpret_cast<const uint32_t*>(&af[mt][2]), b1.x, b1.y);
                MMA_F16(acc[mt][j], reinterpret_cast<const uint32_t*>(&af[mt][3]), b1.z, b1.w);
            }
        }
        __syncwarp();
        if (lane == 0) MBAR_ARRIVE(sb + SM_EMPTY + 8 * s);

        // distributed refill: owner of stage s refills chunk it+STAGES
        if (wid == s && lane == 0 && it + STAGES < K_CHUNKS) {
            MBAR_WAIT(sb + SM_EMPTY + 8 * s, ph);
            MBAR_EXPECT_TX(sb + SM_FULL + 8 * s, CHUNK_BYTES);
            BULK_G2S(sb + SM_A + s * A_STAGE_BYTES, gA + (size_t)(it + STAGES) * A_CHUNK_HALFS, A_STAGE_BYTES, sb + SM_FULL + 8 * s);
            BULK_G2S(sb + SM_B + s * B_STAGE_BYTES, gB + (size_t)(it + STAGES) * B_CHUNK_HALFS, B_STAGE_BYTES, sb + SM_FULL + 8 * s);
        }
        if (++s == STAGES) { s = 0; ph ^= 1; }
    }

    // ---- epilogue: out = acc + bias[n] - c[m] ----
    const int c0 = (lane & 3) * 2;
    const int r0 = lane >> 2;
    const int ncol = nb * TILE_N + wn * 64 + c0;
    float2 bv[8];
#pragma unroll
    for (int j = 0; j < 8; j++) bv[j] = *reinterpret_cast<const float2*>(bias + ncol + j * 8);

    const int mrow = mb * 128 + wm * 32 + r0;
    float cm[4];
#pragma unroll
    for (int i = 0; i < 4; i++) cm[i] = g_c[mrow + i * 8];

#pragma unroll
    for (int mt = 0; mt < 2; mt++) {
#pragma unroll
        for (int h = 0; h < 2; h++) {
            const float cmv = cm[mt * 2 + h];
            float* orow = out + (size_t)(mrow + mt * 16 + h * 8) * N_DIM + ncol;
#pragma unroll
            for (int j = 0; j < 8; j++) {
                float2 v;
                v.x = acc[mt][j][h * 2 + 0] + bv[j].x - cmv;
                v.y = acc[mt][j][h * 2 + 1] + bv[j].y - cmv;
                *reinterpret_cast<float2*>(orow + j * 8) = v;
            }
        }
    }
}

// ---------------- host ----------------
extern "C" void kernel_launch(void* const* d_in, const int* in_sizes, int n_in,
                              void* d_out, int out_size) {
    const float* x      = (const float*)d_in[0];
    const int*   pw     = (const int*)d_in[1];
    const float* scales = (const float*)d_in[2];
    const float* zps    = (const float*)d_in[3];
    const float* bias   = (const float*)d_in[4];
    float* out = (float*)d_out;

    cudaFuncSetAttribute(gemm_kernel, cudaFuncAttributeMaxDynamicSharedMemorySize, SMEM_BYTES);

    prep_c_kernel<<<M_DIM, 256>>>(x, scales, zps);
    prep_x_kernel<<<dim3(128, M_TILES), 256>>>(x, scales);
    prep_w_kernel<<<dim3(128, N_TILES), 256>>>(pw);
    gemm_kernel<<<M_TILES * N_TILES, 256, SMEM_BYTES>>>(bias, out);
}

// round 9
// speedup vs baseline: 2.1020x; 1.0763x over previous
#include <cuda_runtime.h>
#include <cuda_fp16.h>
#include <cstdint>

// ---------------- problem dims ----------------
#define M_DIM 4096
#define K_DIM 4096
#define N_DIM 11008

#define TILE_M 128
#define TILE_N 128
#define TILE_K 64
#define STAGES 3
#define K_CHUNKS (K_DIM / TILE_K)      // 64
#define M_TILES (M_DIM / TILE_M)       // 32
#define N_TILES (N_DIM / TILE_N)       // 86

#define A_CHUNK_HALFS (TILE_M * TILE_K)       // 8192
#define B_CHUNK_HALFS (TILE_N * TILE_K)       // 8192
#define A_STAGE_BYTES (A_CHUNK_HALFS * 2)     // 16384
#define B_STAGE_BYTES (B_CHUNK_HALFS * 2)     // 16384
#define CHUNK_BYTES   (A_STAGE_BYTES + B_STAGE_BYTES)

#define SM_FULL  64
#define SM_EMPTY 128
#define SM_A     1024
#define SM_B     (SM_A + STAGES * A_STAGE_BYTES)       // 50176
#define SMEM_BYTES (SM_B + STAGES * B_STAGE_BYTES)     // 99328  (x2 CTAs = 198656)

// ---------------- scratch (device globals; allocation forbidden) ----------------
// A fragment-major: [mblock(32)][kchunk64(64)][bi(32)][lane(32)] uint4
//   bi = mtile(0..7)*4 + kstep(0..3).  lane's uint4 = a0..a3 of m16n8k16
//   (r=lane>>2, c2=(lane&3)*2):
//   (r,c2),(r,c2+1) | (r+8,c2),(r+8,c2+1) | (r,c2+8),(r,c2+9) | (r+8,c2+8),(r+8,c2+9)
__device__ __half g_xs[(size_t)M_DIM * K_DIM];
// B fragment-major: [nblock(86)][kchunk64(64)][p(16)*2 + kh(2)][lane(32)] uint4
//   p = n8 block (0..15); kh selects ksteps {2kh, 2kh+1}; lane's uint4 =
//   {ks(2kh): b0,b1 | ks(2kh+1): b0,b1}, col n = p*8 + (lane>>2)
__device__ __half g_w[(size_t)N_DIM * K_DIM];
__device__ float g_c[M_DIM];            // c[m] = sum_k x[m,k]*s[g]*zp[g]

// ---------------- PTX helpers (generic features only) ----------------
__device__ __forceinline__ uint32_t smem_u32(const void* p) {
    uint32_t a;
    asm("{ .reg .u64 t; cvta.to.shared.u64 t, %1; cvt.u32.u64 %0, t; }" : "=r"(a) : "l"(p));
    return a;
}

#define MBAR_INIT(addr, cnt) \
    asm volatile("mbarrier.init.shared.b64 [%0], %1;" :: "r"(addr), "r"((uint32_t)(cnt)) : "memory")
#define MBAR_EXPECT_TX(addr, bytes) \
    asm volatile("mbarrier.arrive.expect_tx.shared.b64 _, [%0], %1;" :: "r"(addr), "r"((uint32_t)(bytes)) : "memory")
#define MBAR_ARRIVE(addr) \
    asm volatile("mbarrier.arrive.shared.b64 _, [%0];" :: "r"(addr) : "memory")

#define MBAR_WAIT(addr, parity) do {                                              \
    uint32_t _m = (addr); uint32_t _p = (parity); uint32_t _done;                 \
    asm volatile("{ .reg .pred p;"                                                \
        " mbarrier.try_wait.parity.shared.b64 p, [%1], %2;"                       \
        " selp.b32 %0, 1, 0, p; }" : "=r"(_done) : "r"(_m), "r"(_p) : "memory");  \
    if (!_done) {                                                                 \
        asm volatile("{ .reg .pred P1;"                                           \
            " WL_%=:"                                                             \
            " mbarrier.try_wait.parity.shared.b64 P1, [%0], %1;"                  \
            " @P1 bra.uni WD_%=;"                                                 \
            " bra.uni WL_%=;"                                                     \
            " WD_%=: }" :: "r"(_m), "r"(_p) : "memory");                          \
    }                                                                             \
} while (0)

#define BULK_G2S(dst, src, bytes, mbar)                                           \
    asm volatile("cp.async.bulk.shared::cluster.global.mbarrier::complete_tx::bytes " \
                 "[%0], [%1], %2, [%3];"                                          \
                 :: "r"(dst), "l"(src), "r"((uint32_t)(bytes)), "r"(mbar) : "memory")

#define MMA_F16(acc, au, b0, b1)                                                  \
    asm volatile("mma.sync.aligned.m16n8k16.row.col.f32.f16.f16.f32 "             \
        "{%0,%1,%2,%3}, {%4,%5,%6,%7}, {%8,%9}, {%0,%1,%2,%3};"                   \
        : "+f"((acc)[0]), "+f"((acc)[1]), "+f"((acc)[2]), "+f"((acc)[3])          \
        : "r"((au)[0]), "r"((au)[1]), "r"((au)[2]), "r"((au)[3]),                 \
          "r"(b0), "r"(b1))

__device__ __forceinline__ uint32_t h2u(float lo, float hi) {
    __half2 h = __floats2half2_rn(lo, hi);
    return *reinterpret_cast<uint32_t*>(&h);
}

// ---------------- prep: c[m] = sum_k x[m,k] * s[k/64] * zp[k/64] ----------------
__global__ void __launch_bounds__(256) prep_c_kernel(const float* __restrict__ x,
                                                     const float* __restrict__ scales,
                                                     const float* __restrict__ zps) {
    const int m = blockIdx.x;
    const int tid = threadIdx.x;
    const float4* xr = reinterpret_cast<const float4*>(x + (size_t)m * K_DIM);
    float acc = 0.f;
#pragma unroll
    for (int i = 0; i < 4; i++) {
        int v4 = tid + i * 256;
        int g = v4 >> 4;
        float zs = scales[g] * zps[g];
        float4 v = xr[v4];
        acc += (v.x + v.y + v.z + v.w) * zs;
    }
    __shared__ float red[256];
    red[tid] = acc;
    __syncthreads();
    for (int s = 128; s > 0; s >>= 1) {
        if (tid < s) red[tid] += red[tid + s];
        __syncthreads();
    }
    if (tid == 0) g_c[m] = red[0];
}

// ---------------- prep: x' = fp16(x * s) into fragment-major layout ----------------
__global__ void __launch_bounds__(256) prep_x_kernel(const float* __restrict__ x,
                                                     const float* __restrict__ scales) {
    const int kc = blockIdx.x;             // 32-k granule 0..127
    const int mb = blockIdx.y;
    const int tid = threadIdx.x;
    __shared__ float sm[TILE_M * 32];      // 128x32 floats

    const float s = scales[kc >> 1];       // group = 64 elems = 2 granules
    const float* xsrc = x + (size_t)mb * 128 * K_DIM + kc * 32;
#pragma unroll
    for (int i = 0; i < 16; i++) {
        int idx = tid + i * 256;
        int row = idx >> 5, col = idx & 31;
        sm[idx] = xsrc[(size_t)row * K_DIM + col] * s;
    }
    __syncthreads();

    const int lane = tid & 31, w = tid >> 5;
    uint4* dst = reinterpret_cast<uint4*>(
        g_xs + ((size_t)mb * K_CHUNKS + (kc >> 1)) * A_CHUNK_HALFS);
    const int r = lane >> 2, c2 = (lane & 3) * 2;
    const int khalf = (kc & 1) * 2;        // kstep offset within 64-k chunk
#pragma unroll
    for (int i = 0; i < 2; i++) {
        int blk = w * 2 + i;               // 0..15
        int mt = blk >> 1, ks = blk & 1;
        int rr = mt * 16 + r;
        int k0 = ks * 16 + c2;
        uint4 v;
        v.x = h2u(sm[rr * 32 + k0],           sm[rr * 32 + k0 + 1]);
        v.y = h2u(sm[(rr + 8) * 32 + k0],     sm[(rr + 8) * 32 + k0 + 1]);
        v.z = h2u(sm[rr * 32 + k0 + 8],       sm[rr * 32 + k0 + 9]);
        v.w = h2u(sm[(rr + 8) * 32 + k0 + 8], sm[(rr + 8) * 32 + k0 + 9]);
        dst[(mt * 4 + khalf + ks) * 32 + lane] = v;
    }
}

// ---------------- prep: int4 -> fp16 (exact) into fragment-major layout ----------------
__global__ void __launch_bounds__(256) prep_w_kernel(const int* __restrict__ pw) {
    const int kc = blockIdx.x;             // 32-k granule 0..127
    const int nb = blockIdx.y;             // nblock 0..85 (128 rows each)
    const int tid = threadIdx.x;
    __shared__ float sm[TILE_N * 32];      // 128x32 floats

    const int* src = pw + (size_t)nb * 128 * (K_DIM / 2) + kc * 16;
#pragma unroll
    for (int i = 0; i < 8; i++) {
        int idx = tid + i * 256;           // int32 index 0..2047
        int n = idx >> 4, jj = idx & 15;
        int b = src[(size_t)n * (K_DIM / 2) + jj] & 255;
        sm[n * 32 + jj * 2]     = (float)(((b & 15) ^ 8) - 8);
        sm[n * 32 + jj * 2 + 1] = (float)((((b >> 4) & 15) ^ 8) - 8);
    }
    __syncthreads();

    const int lane = tid & 31, w = tid >> 5;
    uint4* dst = reinterpret_cast<uint4*>(
        g_w + ((size_t)nb * K_CHUNKS + (kc >> 1)) * B_CHUNK_HALFS);
    const int nr = (lane >> 2), c2 = (lane & 3) * 2;
    const int kh = kc & 1;
#pragma unroll
    for (int i = 0; i < 2; i++) {
        int p = w * 2 + i;                 // n8 block 0..15
        int n = p * 8 + nr;
        uint4 v;
        v.x = h2u(sm[n * 32 + c2],      sm[n * 32 + c2 + 1]);
        v.y = h2u(sm[n * 32 + c2 + 8],  sm[n * 32 + c2 + 9]);
        v.z = h2u(sm[n * 32 + 16 + c2], sm[n * 32 + 16 + c2 + 1]);
        v.w = h2u(sm[n * 32 + 24 + c2], sm[n * 32 + 24 + c2 + 1]);
        dst[(p * 2 + kh) * 32 + lane] = v;
    }
}

// ---------------- GEMM: out = x' @ w4^T + (bias - c) ----------------
// 128 threads, 4 warps (2m x 2n), warp tile 64x64, 2 CTAs per SM
__global__ void __launch_bounds__(128, 2) gemm_kernel(const float* __restrict__ bias,
                                                      float* __restrict__ out) {
    extern __shared__ char smem[];
    const uint32_t sb = smem_u32(smem);
    const int tid = threadIdx.x;
    const int lane = tid & 31;
    const int wid = tid >> 5;
    const int wm = wid >> 1;               // 0..1
    const int wn = wid & 1;                // 0..1

    const int bid = blockIdx.x;
    const int nb = bid / M_TILES;          // m fastest: co-resident CTAs share B panel
    const int mb = bid % M_TILES;

    const __half* gA = g_xs + (size_t)mb * K_CHUNKS * A_CHUNK_HALFS;
    const __half* gB = g_w + (size_t)nb * K_CHUNKS * B_CHUNK_HALFS;

    if (tid == 0) {
#pragma unroll
        for (int s = 0; s < STAGES; s++) {
            MBAR_INIT(sb + SM_FULL + 8 * s, 1);
            MBAR_INIT(sb + SM_EMPTY + 8 * s, 4);
        }
        asm volatile("fence.mbarrier_init.release.cluster;" ::: "memory");
    }
    __syncthreads();

    // initial fill: stage s owned by warp s, lane 0
    if (wid < STAGES && lane == 0) {
        const int s = wid;
        MBAR_EXPECT_TX(sb + SM_FULL + 8 * s, CHUNK_BYTES);
        BULK_G2S(sb + SM_A + s * A_STAGE_BYTES, gA + (size_t)s * A_CHUNK_HALFS, A_STAGE_BYTES, sb + SM_FULL + 8 * s);
        BULK_G2S(sb + SM_B + s * B_STAGE_BYTES, gB + (size_t)s * B_CHUNK_HALFS, B_STAGE_BYTES, sb + SM_FULL + 8 * s);
    }

    float acc[4][8][4];
#pragma unroll
    for (int a = 0; a < 4; a++)
#pragma unroll
        for (int b = 0; b < 8; b++)
#pragma unroll
            for (int d = 0; d < 4; d++) acc[a][b][d] = 0.f;

    int s = 0, ph = 0;
    for (int it = 0; it < K_CHUNKS; ++it) {
        MBAR_WAIT(sb + SM_FULL + 8 * s, ph);

        const uint4* As = reinterpret_cast<const uint4*>(smem + SM_A + s * A_STAGE_BYTES);
        const uint4* Bs = reinterpret_cast<const uint4*>(smem + SM_B + s * B_STAGE_BYTES);

#pragma unroll
        for (int kh = 0; kh < 2; kh++) {
            // A frags for this k-half: 4 mtiles x 2 ksteps
            uint4 af[4][2];
#pragma unroll
            for (int mt = 0; mt < 4; mt++)
#pragma unroll
                for (int ks = 0; ks < 2; ks++)
                    af[mt][ks] = As[((wm * 4 + mt) * 4 + kh * 2 + ks) * 32 + lane];

#pragma unroll
            for (int j = 0; j < 8; j++) {
                const int p = wn * 8 + j;
                uint4 bj = Bs[(p * 2 + kh) * 32 + lane];   // ksteps 2kh, 2kh+1
#pragma unroll
                for (int mt = 0; mt < 4; mt++) {
                    MMA_F16(acc[mt][j], reinterpret_cast<const uint32_t*>(&af[mt][0]), bj.x, bj.y);
                    MMA_F16(acc[mt][j], reinterpret_cast<const uint32_t*>(&af[mt][1]), bj.z, bj.w);
                }
            }
        }
        __syncwarp();
        if (lane == 0) MBAR_ARRIVE(sb + SM_EMPTY + 8 * s);

        // distributed refill: owner of stage s refills chunk it+STAGES
        if (wid == s && lane == 0 && it + STAGES < K_CHUNKS) {
            MBAR_WAIT(sb + SM_EMPTY + 8 * s, ph);
            MBAR_EXPECT_TX(sb + SM_FULL + 8 * s, CHUNK_BYTES);
            BULK_G2S(sb + SM_A + s * A_STAGE_BYTES, gA + (size_t)(it + STAGES) * A_CHUNK_HALFS, A_STAGE_BYTES, sb + SM_FULL + 8 * s);
            BULK_G2S(sb + SM_B + s * B_STAGE_BYTES, gB + (size_t)(it + STAGES) * B_CHUNK_HALFS, B_STAGE_BYTES, sb + SM_FULL + 8 * s);
        }
        if (++s == STAGES) { s = 0; ph ^= 1; }
    }

    // ---- epilogue: out = acc + bias[n] - c[m] ----
    const int c0 = (lane & 3) * 2;
    const int r0 = lane >> 2;
    const int ncol = nb * TILE_N + wn * 64 + c0;
    float2 bv[8];
#pragma unroll
    for (int j = 0; j < 8; j++) bv[j] = *reinterpret_cast<const float2*>(bias + ncol + j * 8);

    const int mrow = mb * 128 + wm * 64 + r0;
#pragma unroll
    for (int mt = 0; mt < 4; mt++) {
#pragma unroll
        for (int h = 0; h < 2; h++) {
            const float cmv = g_c[mrow + mt * 16 + h * 8];
            float* orow = out + (size_t)(mrow + mt * 16 + h * 8) * N_DIM + ncol;
#pragma unroll
            for (int j = 0; j < 8; j++) {
                float2 v;
                v.x = acc[mt][j][h * 2 + 0] + bv[j].x - cmv;
                v.y = acc[mt][j][h * 2 + 1] + bv[j].y - cmv;
                *reinterpret_cast<float2*>(orow + j * 8) = v;
            }
        }
    }
}

// ---------------- host ----------------
extern "C" void kernel_launch(void* const* d_in, const int* in_sizes, int n_in,
                              void* d_out, int out_size) {
    const float* x      = (const float*)d_in[0];
    const int*   pw     = (const int*)d_in[1];
    const float* scales = (const float*)d_in[2];
    const float* zps    = (const float*)d_in[3];
    const float* bias   = (const float*)d_in[4];
    float* out = (float*)d_out;

    cudaFuncSetAttribute(gemm_kernel, cudaFuncAttributeMaxDynamicSharedMemorySize, SMEM_BYTES);

    prep_c_kernel<<<M_DIM, 256>>>(x, scales, zps);
    prep_x_kernel<<<dim3(128, M_TILES), 256>>>(x, scales);
    prep_w_kernel<<<dim3(128, N_TILES), 256>>>(pw);
    gemm_kernel<<<M_TILES * N_TILES, 128, SMEM_BYTES>>>(bias, out);
}